// round 11
// baseline (speedup 1.0000x reference)
#include <cuda_runtime.h>
#include <cuda_fp16.h>
#include <math.h>
#include <stdint.h>

#define BATCH 16
#define NP    10000
#define NNB   10
#define NCOL  48
#define BPAD  10016          // padded K for B operand (multiple of 32)
#define BK    32
#define NKT   313            // ceil(10000/32)
#define MT    128
#define NMT   79             // ceil(10000/128)
#define TILES_TOTAL (NMT * NKT)   // 24727
#define NCTA  444            // 148 SMs x 3 CTAs (all resident in wave 1)
#define WBASE (TILES_TOTAL / NCTA)        // 55
#define WREM  (TILES_TOTAL - WBASE * NCTA) // 307
#define NBVB  625            // bvec blocks (16 p each)

// GEMM smem geometry (bytes)
#define AROW  40                       // A row stride in fp32 elems (160 B)
#define BROW  40                       // B row stride in fp16 elems (80 B)
#define A_BYTES (128 * AROW * 4)       // 20480
#define B_BYTES (NCOL * BROW * 2)      // 3840
#define STAGE_BYTES (A_BYTES + B_BYTES)  // 24320
#define NSTAGE 3
#define DSMEM (NSTAGE * STAGE_BYTES)   // 72960

// ---------------- scratch (__device__ globals; zero-init) ------------------
__device__ __align__(16) float g_T[NP * BATCH * 9];   // [p][b][9]
__device__ __align__(16) __half g_bh[NCOL * BPAD];    // B fp16 [c][k]
__device__ int g_flag[NBVB];                          // bvec block ready flags
__device__ int g_c2;                                  // bvec completion counter

__device__ __forceinline__ uint32_t smem_u32(const void* p) {
    uint32_t a;
    asm("{ .reg .u64 t; cvta.to.shared.u64 t, %1; cvt.u32.u64 %0, t; }"
        : "=r"(a) : "l"(p));
    return a;
}

#define LDSM4(r0, r1, r2, r3, addr) \
    asm volatile("ldmatrix.sync.aligned.m8n8.x4.shared.b16 {%0,%1,%2,%3}, [%4];" \
                 : "=r"(r0), "=r"(r1), "=r"(r2), "=r"(r3) : "r"(addr))

#define MMA(d, a0, a1, a2, a3, b0, b1) \
    asm volatile("mma.sync.aligned.m16n8k16.row.col.f32.f16.f16.f32 " \
                 "{%0,%1,%2,%3}, {%4,%5,%6,%7}, {%8,%9}, {%0,%1,%2,%3};" \
                 : "+f"((d)[0]), "+f"((d)[1]), "+f"((d)[2]), "+f"((d)[3]) \
                 : "r"(a0), "r"(a1), "r"(a2), "r"(a3), "r"(b0), "r"(b1))

#define CVT_H2(d, hi, lo) \
    asm("cvt.rn.f16x2.f32 %0, %1, %2;" : "=r"(d) : "f"(hi), "f"(lo))

#define CPA16(dst, src, sz) \
    asm volatile("cp.async.cg.shared.global [%0], [%1], 16, %2;" \
                 :: "r"(dst), "l"(src), "r"(sz) : "memory")
#define CPA_COMMIT() asm volatile("cp.async.commit_group;" ::: "memory")

// ---------------------------------------------------------------------------
// Kernel 1: T[b,p] = R @ S; store [p][b][9]. Zeroes output + resets flags.
// Runs before the fused kernel each replay (stream order) -> flags fresh.
// ---------------------------------------------------------------------------
__global__ __launch_bounds__(256) void ftoT_kernel(const float* __restrict__ geo,
                                                   float4* __restrict__ outz) {
    __shared__ float sT[16 * 145];

    const int tid = threadIdx.x;
    const int bb = tid >> 4;
    const int pi = tid & 15;
    const int p0 = blockIdx.x * 16;
    const int p  = p0 + pi;

    {
        int g = blockIdx.x * 256 + tid;
        if (g < 120000)
            outz[g] = make_float4(0.f, 0.f, 0.f, 0.f);
    }
    if (blockIdx.x == 0) {
        for (int j = tid; j < NBVB; j += 256) g_flag[j] = 0;
        if (tid == 0) g_c2 = 0;
    }

    const float* f = geo + (size_t)(bb * NP + p) * 9;
    float x = f[0], y = f[1], z = f[2];
    float s3 = f[3], s4 = f[4], s5 = f[5], s6 = f[6], s7 = f[7], s8 = f[8];

    float th = sqrtf(x * x + y * y + z * z);
    float R00, R01, R02, R10, R11, R12, R20, R21, R22;
    if (th == 0.0f) {
        R00 = 1.f; R01 = 0.f; R02 = 0.f;
        R10 = 0.f; R11 = 1.f; R12 = 0.f;
        R20 = 0.f; R21 = 0.f; R22 = 1.f;
    } else {
        float inv = 1.0f / th;
        float ka = x * inv, kb = y * inv, kc = z * inv;
        float st, ct;
        __sincosf(th, &st, &ct);
        float omc = 1.0f - ct;
        R00 = 1.0f - omc * (ka * ka + kb * kb);
        R01 =  st * ka - omc * kb * kc;
        R02 =  st * kb + omc * ka * kc;
        R10 = -st * ka - omc * kb * kc;
        R11 = 1.0f - omc * (ka * ka + kc * kc);
        R12 =  st * kc - omc * ka * kb;
        R20 = -st * kb + omc * ka * kc;
        R21 = -st * kc - omc * ka * kb;
        R22 = 1.0f - omc * (kb * kb + kc * kc);
    }
    float* o = sT + pi * 145 + bb * 9;
    o[0] = R00 * s3 + R01 * s4 + R02 * s5;
    o[1] = R00 * s4 + R01 * s6 + R02 * s7;
    o[2] = R00 * s5 + R01 * s7 + R02 * s8;
    o[3] = R10 * s3 + R11 * s4 + R12 * s5;
    o[4] = R10 * s4 + R11 * s6 + R12 * s7;
    o[5] = R10 * s5 + R11 * s7 + R12 * s8;
    o[6] = R20 * s3 + R21 * s4 + R22 * s5;
    o[7] = R20 * s4 + R21 * s6 + R22 * s7;
    o[8] = R20 * s5 + R21 * s7 + R22 * s8;
    __syncthreads();

    float4* dst = reinterpret_cast<float4*>(g_T + (size_t)p0 * 144);
#pragma unroll
    for (int q = tid; q < 576; q += 256) {
        int prow = q / 36;
        int s = q - prow * 36;
        const float* sp = sT + prow * 145 + s * 4;
        dst[q] = make_float4(sp[0], sp[1], sp[2], sp[3]);
    }
}

// ---------------------------------------------------------------------------
// Kernel 2 (fused): bvec phase (flag-publishing) + stream-K fp16 GEMM with
// per-tile flag-gated B loads. A loads stream ungated from the start.
// ---------------------------------------------------------------------------
__global__ __launch_bounds__(256, 3) void bvec_gemm(const int* __restrict__ nb,
                                                    const float* __restrict__ vdiff,
                                                    const float* __restrict__ A,
                                                    float* __restrict__ out) {
    extern __shared__ __align__(16) char dsm[];

    const int t = threadIdx.x;
    const int w = t >> 5;
    const int l = t & 31;

    // ================= phase 1: bvec blocks ===============================
    {
        int* s_nb  = reinterpret_cast<int*>(dsm);           // 160 ints
        float* s_vd = reinterpret_cast<float*>(dsm + 1024); // 480 floats
        const int bb = t & 15;
        const int pi = t >> 4;

        for (int j = blockIdx.x; j < NBVB; j += NCTA) {
            const int p0 = j * 16;
            const int p  = p0 + pi;

            if (t < 160) s_nb[t] = __ldg(nb + p0 * NNB + t);
            if (t < 120) {
                float4 v = __ldg(reinterpret_cast<const float4*>(vdiff + (size_t)p0 * 30) + t);
                *reinterpret_cast<float4*>(&s_vd[t * 4]) = v;
            }
            __syncthreads();

            const float* Tp = g_T + ((size_t)p * BATCH + bb) * 9;
            float T0 = Tp[0], T1 = Tp[1], T2 = Tp[2];
            float T3 = Tp[3], T4 = Tp[4], T5 = Tp[5];
            float T6 = Tp[6], T7 = Tp[7], T8 = Tp[8];

            float a0 = 0.f, a1 = 0.f, a2 = 0.f;
            float v0s = 0.f, v1s = 0.f, v2s = 0.f;

#pragma unroll
            for (int n = 0; n < NNB; n++) {
                int idx = s_nb[pi * NNB + n];
                float v0 = s_vd[pi * 30 + n * 3 + 0];
                float v1 = s_vd[pi * 30 + n * 3 + 1];
                float v2 = s_vd[pi * 30 + n * 3 + 2];
                v0s += v0; v1s += v1; v2s += v2;
                if (idx > 0) {
                    const float* Tn = g_T + ((size_t)(idx - 1) * BATCH + bb) * 9;
                    a0 += Tn[0] * v0 + Tn[1] * v1 + Tn[2] * v2;
                    a1 += Tn[3] * v0 + Tn[4] * v1 + Tn[5] * v2;
                    a2 += Tn[6] * v0 + Tn[7] * v1 + Tn[8] * v2;
                }
            }
            a0 += T0 * v0s + T1 * v1s + T2 * v2s;
            a1 += T3 * v0s + T4 * v1s + T5 * v2s;
            a2 += T6 * v0s + T7 * v1s + T8 * v2s;

            int c = bb * 3;
            g_bh[(size_t)(c + 0) * BPAD + p] = __float2half_rn(a0);
            g_bh[(size_t)(c + 1) * BPAD + p] = __float2half_rn(a1);
            g_bh[(size_t)(c + 2) * BPAD + p] = __float2half_rn(a2);

            __threadfence();
            __syncthreads();
            if (t == 0) {
                atomicExch(&g_flag[j], 1);
                atomicAdd(&g_c2, 1);
            }
            __syncthreads();
        }
    }
    __syncthreads();

    // ================= phase 2: stream-K GEMM =============================
    const int g   = l >> 2;
    const int tig = l & 3;
    const int mat = l >> 3, mrow = l & 7;

    const uint32_t smb = smem_u32(dsm);
    const int b_off = (((mat >> 1) << 3) + mrow) * BROW + ((mat & 1) << 3);

    const bool bldr = (t < 192);        // warps 0..5 load B
    const int br = t >> 2, bseg = t & 3;

    bool all_ready = false;             // meaningful on lane 0 of warps 0..5

    const int ct = blockIdx.x;
    int start = ct * WBASE + (ct < WREM ? ct : WREM);
    int remn  = WBASE + (ct < WREM ? 1 : 0);

    while (remn > 0) {
        const int m   = start / NKT;
        const int kti = start - m * NKT;
        int seg = NKT - kti; if (seg > remn) seg = remn;
        const int row0 = m * MT;

        float acc[6][4];
#pragma unroll
        for (int i = 0; i < 6; i++)
#pragma unroll
            for (int j = 0; j < 4; j++) acc[i][j] = 0.f;

        auto issue_tile = [&](int i) {
            int kt = kti + i;
            int k0 = kt * BK;
            int st = i % NSTAGE;
            uint32_t abase = smb + st * STAGE_BYTES;
            uint32_t bbase = abase + A_BYTES;
            // A loads: ungated
#pragma unroll
            for (int j = 0; j < 4; j++) {
                int q = j * 256 + t;
                int r = q >> 3, c = q & 7;
                int grow = row0 + r, gk = k0 + c * 4;
                uint32_t sz = (grow < NP && gk < NP) ? 16u : 0u;
                CPA16(abase + (uint32_t)(r * AROW + c * 4) * 4,
                      A + (size_t)grow * NP + gk, sz);
            }
            // B loads: gated on bvec flags for this k-range
            if (bldr) {
                if (l == 0 && !all_ready) {
                    if (atomicAdd(&g_c2, 0) >= NBVB) {
                        all_ready = true;
                    } else {
                        int f0 = 2 * kt;
                        int f1 = 2 * kt + 1; if (f1 > NBVB - 1) f1 = NBVB - 1;
                        while (atomicAdd(&g_flag[f0], 0) == 0) __nanosleep(128);
                        while (atomicAdd(&g_flag[f1], 0) == 0) __nanosleep(128);
                    }
                }
                __syncwarp();
                CPA16(bbase + (uint32_t)(br * BROW + bseg * 8) * 2,
                      g_bh + (size_t)br * BPAD + k0 + bseg * 8, 16u);
            }
            CPA_COMMIT();
        };

        issue_tile(0);
        if (seg > 1) issue_tile(1);
        else CPA_COMMIT();

        for (int i = 0; i < seg; i++) {
            if (i + 1 < seg) {
                asm volatile("cp.async.wait_group 1;" ::: "memory");
            } else {
                asm volatile("cp.async.wait_group 0;" ::: "memory");
            }
            __syncthreads();
            if (i + 2 < seg) issue_tile(i + 2);

            int st = i % NSTAGE;
            const float* smA = reinterpret_cast<const float*>(dsm + st * STAGE_BYTES);
            uint32_t bb2 = smb + st * STAGE_BYTES + A_BYTES;

#pragma unroll
            for (int ks = 0; ks < 2; ks++) {
                const int c0 = ks * 16 + tig * 2;
                const float2 v0 = *reinterpret_cast<const float2*>(&smA[(w * 16 + g) * AROW + c0]);
                const float2 v1 = *reinterpret_cast<const float2*>(&smA[(w * 16 + g + 8) * AROW + c0]);
                const float2 v2 = *reinterpret_cast<const float2*>(&smA[(w * 16 + g) * AROW + c0 + 8]);
                const float2 v3 = *reinterpret_cast<const float2*>(&smA[(w * 16 + g + 8) * AROW + c0 + 8]);
                uint32_t a0, a1, a2, a3;
                CVT_H2(a0, v0.y, v0.x);
                CVT_H2(a1, v1.y, v1.x);
                CVT_H2(a2, v2.y, v2.x);
                CVT_H2(a3, v3.y, v3.x);
                int kk = ks * 16;
#pragma unroll
                for (int ntp = 0; ntp < 3; ntp++) {
                    uint32_t b0, b1, b2, b3;
                    uint32_t boff = (uint32_t)(b_off + ntp * 16 * BROW + kk) * 2;
                    LDSM4(b0, b1, b2, b3, bb2 + boff);
                    MMA(acc[ntp * 2],     a0, a1, a2, a3, b0, b1);
                    MMA(acc[ntp * 2 + 1], a0, a1, a2, a3, b2, b3);
                }
            }
        }

        const int v0r = row0 + w * 16 + g;
#pragma unroll
        for (int nt = 0; nt < 6; nt++) {
            int c0 = nt * 8 + tig * 2;
#pragma unroll
            for (int half = 0; half < 2; half++) {
                int v = v0r + half * 8;
                if (v < NP) {
#pragma unroll
                    for (int e2 = 0; e2 < 2; e2++) {
                        int c = c0 + e2;
                        int bo = c / 3, e = c - bo * 3;
                        atomicAdd(out + (size_t)bo * NP * 3 + (size_t)v * 3 + e,
                                  acc[nt][half * 2 + e2]);
                    }
                }
            }
        }

        start += seg;
        remn  -= seg;
        if (remn > 0) __syncthreads();
    }
}

// ---------------------------------------------------------------------------
extern "C" void kernel_launch(void* const* d_in, const int* in_sizes, int n_in,
                              void* d_out, int out_size) {
    const float* geo   = (const float*)d_in[0];
    const int*   nb    = (const int*)d_in[1];
    const float* recon = (const float*)d_in[2];
    const float* vdiff = (const float*)d_in[3];
    float* out = (float*)d_out;

    cudaFuncSetAttribute(bvec_gemm, cudaFuncAttributeMaxDynamicSharedMemorySize,
                         DSMEM);

    ftoT_kernel<<<NP / 16, 256>>>(geo, reinterpret_cast<float4*>(out));
    bvec_gemm<<<NCTA, 256, DSMEM>>>(nb, vdiff, recon, out);
}

// round 13
// speedup vs baseline: 1.1274x; 1.1274x over previous
#include <cuda_runtime.h>
#include <cuda_fp16.h>
#include <math.h>
#include <stdint.h>

#define BATCH 16
#define NP    10000
#define NNB   10
#define NCOL  48
#define BPAD  10016          // padded K for B operand (multiple of 32)
#define BK    32
#define NKT   313            // ceil(10000/32)
#define MT    128
#define NMT   79             // ceil(10000/128)
#define TILES_TOTAL (NMT * NKT)   // 24727
#define NCTA  592            // 148 SMs x 4 CTAs
#define WBASE (TILES_TOTAL / NCTA)        // 41
#define WREM  (TILES_TOTAL - WBASE * NCTA) // 455

// GEMM smem geometry (bytes)
#define AROW  40                       // A row stride in fp32 elems (160 B)
#define BROW  40                       // B row stride in fp16 elems (80 B)
#define A_BYTES (128 * AROW * 4)       // 20480
#define B_BYTES (NCOL * BROW * 2)      // 3840
#define STAGE_BYTES (A_BYTES + B_BYTES)  // 24320
#define NSTAGE 2
#define DSMEM (NSTAGE * STAGE_BYTES)   // 48640  -> 4 CTAs/SM = 194.5 KB

// ---------------- scratch (__device__ globals; zero-init) ------------------
__device__ __align__(16) float g_T[NP * BATCH * 9];   // [p][b][9]
__device__ __align__(16) __half g_bh[NCOL * BPAD];    // B fp16 [c][k]

__device__ __forceinline__ uint32_t smem_u32(const void* p) {
    uint32_t a;
    asm("{ .reg .u64 t; cvta.to.shared.u64 t, %1; cvt.u32.u64 %0, t; }"
        : "=r"(a) : "l"(p));
    return a;
}

#define LDSM4(r0, r1, r2, r3, addr) \
    asm volatile("ldmatrix.sync.aligned.m8n8.x4.shared.b16 {%0,%1,%2,%3}, [%4];" \
                 : "=r"(r0), "=r"(r1), "=r"(r2), "=r"(r3) : "r"(addr))

#define MMA(d, a0, a1, a2, a3, b0, b1) \
    asm volatile("mma.sync.aligned.m16n8k16.row.col.f32.f16.f16.f32 " \
                 "{%0,%1,%2,%3}, {%4,%5,%6,%7}, {%8,%9}, {%0,%1,%2,%3};" \
                 : "+f"((d)[0]), "+f"((d)[1]), "+f"((d)[2]), "+f"((d)[3]) \
                 : "r"(a0), "r"(a1), "r"(a2), "r"(a3), "r"(b0), "r"(b1))

#define CVT_H2(d, hi, lo) \
    asm("cvt.rn.f16x2.f32 %0, %1, %2;" : "=r"(d) : "f"(hi), "f"(lo))

#define CPA16(dst, src, sz) \
    asm volatile("cp.async.cg.shared.global [%0], [%1], 16, %2;" \
                 :: "r"(dst), "l"(src), "r"(sz) : "memory")
#define CPA_COMMIT() asm volatile("cp.async.commit_group;" ::: "memory")

// ---------------------------------------------------------------------------
// Kernel 1: T[b,p] = R @ S; store [p][b][9]. Zeroes output.
// ---------------------------------------------------------------------------
__global__ __launch_bounds__(256) void ftoT_kernel(const float* __restrict__ geo,
                                                   float4* __restrict__ outz) {
    __shared__ float sT[16 * 145];

    const int tid = threadIdx.x;
    const int bb = tid >> 4;
    const int pi = tid & 15;
    const int p0 = blockIdx.x * 16;
    const int p  = p0 + pi;

    {
        int g = blockIdx.x * 256 + tid;
        if (g < 120000)
            outz[g] = make_float4(0.f, 0.f, 0.f, 0.f);
    }

    const float* f = geo + (size_t)(bb * NP + p) * 9;
    float x = f[0], y = f[1], z = f[2];
    float s3 = f[3], s4 = f[4], s5 = f[5], s6 = f[6], s7 = f[7], s8 = f[8];

    float th = sqrtf(x * x + y * y + z * z);
    float R00, R01, R02, R10, R11, R12, R20, R21, R22;
    if (th == 0.0f) {
        R00 = 1.f; R01 = 0.f; R02 = 0.f;
        R10 = 0.f; R11 = 1.f; R12 = 0.f;
        R20 = 0.f; R21 = 0.f; R22 = 1.f;
    } else {
        float inv = 1.0f / th;
        float ka = x * inv, kb = y * inv, kc = z * inv;
        float st, ct;
        __sincosf(th, &st, &ct);
        float omc = 1.0f - ct;
        R00 = 1.0f - omc * (ka * ka + kb * kb);
        R01 =  st * ka - omc * kb * kc;
        R02 =  st * kb + omc * ka * kc;
        R10 = -st * ka - omc * kb * kc;
        R11 = 1.0f - omc * (ka * ka + kc * kc);
        R12 =  st * kc - omc * ka * kb;
        R20 = -st * kb + omc * ka * kc;
        R21 = -st * kc - omc * ka * kb;
        R22 = 1.0f - omc * (kb * kb + kc * kc);
    }
    float* o = sT + pi * 145 + bb * 9;
    o[0] = R00 * s3 + R01 * s4 + R02 * s5;
    o[1] = R00 * s4 + R01 * s6 + R02 * s7;
    o[2] = R00 * s5 + R01 * s7 + R02 * s8;
    o[3] = R10 * s3 + R11 * s4 + R12 * s5;
    o[4] = R10 * s4 + R11 * s6 + R12 * s7;
    o[5] = R10 * s5 + R11 * s7 + R12 * s8;
    o[6] = R20 * s3 + R21 * s4 + R22 * s5;
    o[7] = R20 * s4 + R21 * s6 + R22 * s7;
    o[8] = R20 * s5 + R21 * s7 + R22 * s8;
    __syncthreads();

    float4* dst = reinterpret_cast<float4*>(g_T + (size_t)p0 * 144);
#pragma unroll
    for (int q = tid; q < 576; q += 256) {
        int prow = q / 36;
        int s = q - prow * 36;
        const float* sp = sT + prow * 145 + s * 4;
        dst[q] = make_float4(sp[0], sp[1], sp[2], sp[3]);
    }
}

// ---------------------------------------------------------------------------
// Kernel 2: bvec (smem-staged nb/vdiff) -> g_bh[c][k].
// ---------------------------------------------------------------------------
__global__ __launch_bounds__(256) void bvec_kernel(const int* __restrict__ nb,
                                                   const float* __restrict__ vdiff) {
    __shared__ int   s_nb[160];    // 16 p x 10
    __shared__ float s_vd[480];    // 16 p x 30

    const int tid = threadIdx.x;
    const int bb = tid & 15;
    const int pi = tid >> 4;
    const int p0 = blockIdx.x * 16;
    const int p  = p0 + pi;

    if (tid < 160) s_nb[tid] = __ldg(nb + p0 * NNB + tid);
    if (tid < 120) {
        float4 v = __ldg(reinterpret_cast<const float4*>(vdiff + (size_t)p0 * 30) + tid);
        *reinterpret_cast<float4*>(&s_vd[tid * 4]) = v;
    }
    __syncthreads();

    const float* Tp = g_T + ((size_t)p * BATCH + bb) * 9;
    float T0 = Tp[0], T1 = Tp[1], T2 = Tp[2];
    float T3 = Tp[3], T4 = Tp[4], T5 = Tp[5];
    float T6 = Tp[6], T7 = Tp[7], T8 = Tp[8];

    float a0 = 0.f, a1 = 0.f, a2 = 0.f;
    float v0s = 0.f, v1s = 0.f, v2s = 0.f;

#pragma unroll
    for (int n = 0; n < NNB; n++) {
        int idx = s_nb[pi * NNB + n];
        float v0 = s_vd[pi * 30 + n * 3 + 0];
        float v1 = s_vd[pi * 30 + n * 3 + 1];
        float v2 = s_vd[pi * 30 + n * 3 + 2];
        v0s += v0; v1s += v1; v2s += v2;
        if (idx > 0) {
            const float* Tn = g_T + ((size_t)(idx - 1) * BATCH + bb) * 9;
            a0 += Tn[0] * v0 + Tn[1] * v1 + Tn[2] * v2;
            a1 += Tn[3] * v0 + Tn[4] * v1 + Tn[5] * v2;
            a2 += Tn[6] * v0 + Tn[7] * v1 + Tn[8] * v2;
        }
    }
    a0 += T0 * v0s + T1 * v1s + T2 * v2s;
    a1 += T3 * v0s + T4 * v1s + T5 * v2s;
    a2 += T6 * v0s + T7 * v1s + T8 * v2s;

    int c = bb * 3;
    g_bh[(size_t)(c + 0) * BPAD + p] = __float2half_rn(a0);
    g_bh[(size_t)(c + 1) * BPAD + p] = __float2half_rn(a1);
    g_bh[(size_t)(c + 2) * BPAD + p] = __float2half_rn(a2);
}

// ---------------------------------------------------------------------------
// Kernel 3: stream-K fp16 GEMM. 2-stage cp.async pipeline, 4 CTAs/SM.
// ---------------------------------------------------------------------------
__global__ __launch_bounds__(256, 4) void gemm_mma(const float* __restrict__ A,
                                                   float* __restrict__ out) {
    extern __shared__ __align__(16) char dsm[];

    const int t = threadIdx.x;
    const int w = t >> 5;
    const int l = t & 31;

    const int g   = l >> 2;
    const int tig = l & 3;
    const int mat = l >> 3, mrow = l & 7;

    const uint32_t smb = smem_u32(dsm);
    const int b_off = (((mat >> 1) << 3) + mrow) * BROW + ((mat & 1) << 3);

    const bool bldr = (t < 192);
    const int br = t >> 2, bseg = t & 3;

    const int ct = blockIdx.x;
    int start = ct * WBASE + (ct < WREM ? ct : WREM);
    int remn  = WBASE + (ct < WREM ? 1 : 0);

    while (remn > 0) {
        const int m   = start / NKT;
        const int kti = start - m * NKT;
        int seg = NKT - kti; if (seg > remn) seg = remn;
        const int row0 = m * MT;

        float acc[6][4];
#pragma unroll
        for (int i = 0; i < 6; i++)
#pragma unroll
            for (int j = 0; j < 4; j++) acc[i][j] = 0.f;

        auto issue_tile = [&](int i) {
            int k0 = (kti + i) * BK;
            uint32_t abase = smb + (uint32_t)((i & 1) * STAGE_BYTES);
            uint32_t bbase = abase + A_BYTES;
#pragma unroll
            for (int j = 0; j < 4; j++) {
                int q = j * 256 + t;
                int r = q >> 3, c = q & 7;
                int grow = row0 + r, gk = k0 + c * 4;
                uint32_t sz = (grow < NP && gk < NP) ? 16u : 0u;
                CPA16(abase + (uint32_t)(r * AROW + c * 4) * 4,
                      A + (size_t)grow * NP + gk, sz);
            }
            if (bldr) {
                CPA16(bbase + (uint32_t)(br * BROW + bseg * 8) * 2,
                      g_bh + (size_t)br * BPAD + k0 + bseg * 8, 16u);
            }
            CPA_COMMIT();
        };

        issue_tile(0);
        if (seg > 1) issue_tile(1);
        else CPA_COMMIT();

        for (int i = 0; i < seg; i++) {
            if (i + 1 < seg) {
                asm volatile("cp.async.wait_group 1;" ::: "memory");
            } else {
                asm volatile("cp.async.wait_group 0;" ::: "memory");
            }
            __syncthreads();

            const uint32_t sbase = smb + (uint32_t)((i & 1) * STAGE_BYTES);
            const float* smA = reinterpret_cast<const float*>(dsm + (i & 1) * STAGE_BYTES);
            const uint32_t bb2 = sbase + A_BYTES;

#pragma unroll
            for (int ks = 0; ks < 2; ks++) {
                const int c0 = ks * 16 + tig * 2;
                const float2 v0 = *reinterpret_cast<const float2*>(&smA[(w * 16 + g) * AROW + c0]);
                const float2 v1 = *reinterpret_cast<const float2*>(&smA[(w * 16 + g + 8) * AROW + c0]);
                const float2 v2 = *reinterpret_cast<const float2*>(&smA[(w * 16 + g) * AROW + c0 + 8]);
                const float2 v3 = *reinterpret_cast<const float2*>(&smA[(w * 16 + g + 8) * AROW + c0 + 8]);
                uint32_t a0, a1, a2, a3;
                CVT_H2(a0, v0.y, v0.x);
                CVT_H2(a1, v1.y, v1.x);
                CVT_H2(a2, v2.y, v2.x);
                CVT_H2(a3, v3.y, v3.x);
                int kk = ks * 16;
#pragma unroll
                for (int ntp = 0; ntp < 3; ntp++) {
                    uint32_t b0, b1, b2, b3;
                    uint32_t boff = (uint32_t)(b_off + ntp * 16 * BROW + kk) * 2;
                    LDSM4(b0, b1, b2, b3, bb2 + boff);
                    MMA(acc[ntp * 2],     a0, a1, a2, a3, b0, b1);
                    MMA(acc[ntp * 2 + 1], a0, a1, a2, a3, b2, b3);
                }
            }
            // stage (i&1) fully consumed; safe to refill with tile i+2
            __syncthreads();
            if (i + 2 < seg) issue_tile(i + 2);
        }

        const int v0r = row0 + w * 16 + g;
#pragma unroll
        for (int nt = 0; nt < 6; nt++) {
            int c0 = nt * 8 + tig * 2;
#pragma unroll
            for (int half = 0; half < 2; half++) {
                int v = v0r + half * 8;
                if (v < NP) {
#pragma unroll
                    for (int e2 = 0; e2 < 2; e2++) {
                        int c = c0 + e2;
                        int bo = c / 3, e = c - bo * 3;
                        atomicAdd(out + (size_t)bo * NP * 3 + (size_t)v * 3 + e,
                                  acc[nt][half * 2 + e2]);
                    }
                }
            }
        }

        start += seg;
        remn  -= seg;
        if (remn > 0) __syncthreads();
    }
}

// ---------------------------------------------------------------------------
extern "C" void kernel_launch(void* const* d_in, const int* in_sizes, int n_in,
                              void* d_out, int out_size) {
    const float* geo   = (const float*)d_in[0];
    const int*   nb    = (const int*)d_in[1];
    const float* recon = (const float*)d_in[2];
    const float* vdiff = (const float*)d_in[3];
    float* out = (float*)d_out;

    cudaFuncSetAttribute(gemm_mma, cudaFuncAttributeMaxDynamicSharedMemorySize,
                         DSMEM);

    ftoT_kernel<<<NP / 16, 256>>>(geo, reinterpret_cast<float4*>(out));
    bvec_kernel<<<NP / 16, 256>>>(nb, vdiff);
    gemm_mma<<<NCTA, 256, DSMEM>>>(recon, out);
}

// round 14
// speedup vs baseline: 1.1469x; 1.0173x over previous
#include <cuda_runtime.h>
#include <cuda_fp16.h>
#include <math.h>
#include <stdint.h>

#define BATCH 16
#define NP    10000
#define NNB   10
#define NCOL  48
#define BPAD  10048          // padded K for B operand (multiple of 64)
#define BK    64
#define NKT   157            // ceil(10000/64)
#define MT    128
#define NMT   79
#define TILES_TOTAL (NMT * NKT)   // 12403
#define NCTA  296            // 148 SMs x 2 CTAs
#define WBASE (TILES_TOTAL / NCTA)        // 41
#define WREM  (TILES_TOTAL - WBASE * NCTA) // 267

// GEMM smem geometry
#define AROW  72                       // A row stride in fp32 elems (288 B)
#define BROW  72                       // B row stride in fp16 elems (144 B)
#define A_BYTES (128 * AROW * 4)       // 36864
#define B_BYTES (NCOL * BROW * 2)      // 6912
#define STAGE_BYTES (A_BYTES + B_BYTES)  // 43776
#define NSTAGE 2
#define DSMEM (NSTAGE * STAGE_BYTES)   // 87552 -> 2 CTAs/SM = 175 KB

// ---------------- scratch (__device__ globals; zero-init) ------------------
__device__ __align__(16) float g_T[NP * BATCH * 9];   // [p][b][9]
__device__ __align__(16) __half g_bh[NCOL * BPAD];    // B fp16 [c][k]

__device__ __forceinline__ uint32_t smem_u32(const void* p) {
    uint32_t a;
    asm("{ .reg .u64 t; cvta.to.shared.u64 t, %1; cvt.u32.u64 %0, t; }"
        : "=r"(a) : "l"(p));
    return a;
}

#define LDSM4(r0, r1, r2, r3, addr) \
    asm volatile("ldmatrix.sync.aligned.m8n8.x4.shared.b16 {%0,%1,%2,%3}, [%4];" \
                 : "=r"(r0), "=r"(r1), "=r"(r2), "=r"(r3) : "r"(addr))

#define MMA(d, a0, a1, a2, a3, b0, b1) \
    asm volatile("mma.sync.aligned.m16n8k16.row.col.f32.f16.f16.f32 " \
                 "{%0,%1,%2,%3}, {%4,%5,%6,%7}, {%8,%9}, {%0,%1,%2,%3};" \
                 : "+f"((d)[0]), "+f"((d)[1]), "+f"((d)[2]), "+f"((d)[3]) \
                 : "r"(a0), "r"(a1), "r"(a2), "r"(a3), "r"(b0), "r"(b1))

#define CVT_H2(d, hi, lo) \
    asm("cvt.rn.f16x2.f32 %0, %1, %2;" : "=r"(d) : "f"(hi), "f"(lo))

#define CPA16(dst, src, sz) \
    asm volatile("cp.async.cg.shared.global [%0], [%1], 16, %2;" \
                 :: "r"(dst), "l"(src), "r"(sz) : "memory")
#define CPA16U(dst, src) \
    asm volatile("cp.async.cg.shared.global [%0], [%1], 16;" \
                 :: "r"(dst), "l"(src) : "memory")
#define CPA_COMMIT() asm volatile("cp.async.commit_group;" ::: "memory")

// ---------------------------------------------------------------------------
// Kernel 1: T[b,p] = R @ S; store [p][b][9]. Zeroes output.
// ---------------------------------------------------------------------------
__global__ __launch_bounds__(256) void ftoT_kernel(const float* __restrict__ geo,
                                                   float4* __restrict__ outz) {
    __shared__ float sT[16 * 145];

    const int tid = threadIdx.x;
    const int bb = tid >> 4;
    const int pi = tid & 15;
    const int p0 = blockIdx.x * 16;
    const int p  = p0 + pi;

    {
        int g = blockIdx.x * 256 + tid;
        if (g < 120000)
            outz[g] = make_float4(0.f, 0.f, 0.f, 0.f);
    }

    const float* f = geo + (size_t)(bb * NP + p) * 9;
    float x = f[0], y = f[1], z = f[2];
    float s3 = f[3], s4 = f[4], s5 = f[5], s6 = f[6], s7 = f[7], s8 = f[8];

    float th = sqrtf(x * x + y * y + z * z);
    float R00, R01, R02, R10, R11, R12, R20, R21, R22;
    if (th == 0.0f) {
        R00 = 1.f; R01 = 0.f; R02 = 0.f;
        R10 = 0.f; R11 = 1.f; R12 = 0.f;
        R20 = 0.f; R21 = 0.f; R22 = 1.f;
    } else {
        float inv = 1.0f / th;
        float ka = x * inv, kb = y * inv, kc = z * inv;
        float st, ct;
        __sincosf(th, &st, &ct);
        float omc = 1.0f - ct;
        R00 = 1.0f - omc * (ka * ka + kb * kb);
        R01 =  st * ka - omc * kb * kc;
        R02 =  st * kb + omc * ka * kc;
        R10 = -st * ka - omc * kb * kc;
        R11 = 1.0f - omc * (ka * ka + kc * kc);
        R12 =  st * kc - omc * ka * kb;
        R20 = -st * kb + omc * ka * kc;
        R21 = -st * kc - omc * ka * kb;
        R22 = 1.0f - omc * (kb * kb + kc * kc);
    }
    float* o = sT + pi * 145 + bb * 9;
    o[0] = R00 * s3 + R01 * s4 + R02 * s5;
    o[1] = R00 * s4 + R01 * s6 + R02 * s7;
    o[2] = R00 * s5 + R01 * s7 + R02 * s8;
    o[3] = R10 * s3 + R11 * s4 + R12 * s5;
    o[4] = R10 * s4 + R11 * s6 + R12 * s7;
    o[5] = R10 * s5 + R11 * s7 + R12 * s8;
    o[6] = R20 * s3 + R21 * s4 + R22 * s5;
    o[7] = R20 * s4 + R21 * s6 + R22 * s7;
    o[8] = R20 * s5 + R21 * s7 + R22 * s8;
    __syncthreads();

    float4* dst = reinterpret_cast<float4*>(g_T + (size_t)p0 * 144);
#pragma unroll
    for (int q = tid; q < 576; q += 256) {
        int prow = q / 36;
        int s = q - prow * 36;
        const float* sp = sT + prow * 145 + s * 4;
        dst[q] = make_float4(sp[0], sp[1], sp[2], sp[3]);
    }
}

// ---------------------------------------------------------------------------
// Kernel 2: bvec (smem-staged nb/vdiff) -> g_bh[c][k].
// ---------------------------------------------------------------------------
__global__ __launch_bounds__(256) void bvec_kernel(const int* __restrict__ nb,
                                                   const float* __restrict__ vdiff) {
    __shared__ int   s_nb[160];    // 16 p x 10
    __shared__ float s_vd[480];    // 16 p x 30

    const int tid = threadIdx.x;
    const int bb = tid & 15;
    const int pi = tid >> 4;
    const int p0 = blockIdx.x * 16;
    const int p  = p0 + pi;

    if (tid < 160) s_nb[tid] = __ldg(nb + p0 * NNB + tid);
    if (tid < 120) {
        float4 v = __ldg(reinterpret_cast<const float4*>(vdiff + (size_t)p0 * 30) + tid);
        *reinterpret_cast<float4*>(&s_vd[tid * 4]) = v;
    }
    __syncthreads();

    const float* Tp = g_T + ((size_t)p * BATCH + bb) * 9;
    float T0 = Tp[0], T1 = Tp[1], T2 = Tp[2];
    float T3 = Tp[3], T4 = Tp[4], T5 = Tp[5];
    float T6 = Tp[6], T7 = Tp[7], T8 = Tp[8];

    float a0 = 0.f, a1 = 0.f, a2 = 0.f;
    float v0s = 0.f, v1s = 0.f, v2s = 0.f;

#pragma unroll
    for (int n = 0; n < NNB; n++) {
        int idx = s_nb[pi * NNB + n];
        float v0 = s_vd[pi * 30 + n * 3 + 0];
        float v1 = s_vd[pi * 30 + n * 3 + 1];
        float v2 = s_vd[pi * 30 + n * 3 + 2];
        v0s += v0; v1s += v1; v2s += v2;
        if (idx > 0) {
            const float* Tn = g_T + ((size_t)(idx - 1) * BATCH + bb) * 9;
            a0 += Tn[0] * v0 + Tn[1] * v1 + Tn[2] * v2;
            a1 += Tn[3] * v0 + Tn[4] * v1 + Tn[5] * v2;
            a2 += Tn[6] * v0 + Tn[7] * v1 + Tn[8] * v2;
        }
    }
    a0 += T0 * v0s + T1 * v1s + T2 * v2s;
    a1 += T3 * v0s + T4 * v1s + T5 * v2s;
    a2 += T6 * v0s + T7 * v1s + T8 * v2s;

    int c = bb * 3;
    g_bh[(size_t)(c + 0) * BPAD + p] = __float2half_rn(a0);
    g_bh[(size_t)(c + 1) * BPAD + p] = __float2half_rn(a1);
    g_bh[(size_t)(c + 2) * BPAD + p] = __float2half_rn(a2);
}

// ---------------------------------------------------------------------------
// Kernel 3: stream-K fp16 GEMM, BK=64 (256B DRAM bursts/row), 2-stage,
// 2 CTAs/SM. M=10000, N=48, K=10000.
// ---------------------------------------------------------------------------
__global__ __launch_bounds__(256, 2) void gemm_mma(const float* __restrict__ A,
                                                   float* __restrict__ out) {
    extern __shared__ __align__(16) char dsm[];

    const int t = threadIdx.x;
    const int w = t >> 5;
    const int l = t & 31;

    const int g   = l >> 2;
    const int tig = l & 3;
    const int mat = l >> 3, mrow = l & 7;

    const uint32_t smb = smem_u32(dsm);
    const int b_off = (((mat >> 1) << 3) + mrow) * BROW + ((mat & 1) << 3);

    const int ct = blockIdx.x;
    int start = ct * WBASE + (ct < WREM ? ct : WREM);
    int remn  = WBASE + (ct < WREM ? 1 : 0);

    while (remn > 0) {
        const int m   = start / NKT;
        const int kti = start - m * NKT;
        int seg = NKT - kti; if (seg > remn) seg = remn;
        const int row0 = m * MT;
        const bool m_edge = (row0 + MT > NP);

        float acc[6][4];
#pragma unroll
        for (int i = 0; i < 6; i++)
#pragma unroll
            for (int j = 0; j < 4; j++) acc[i][j] = 0.f;

        auto issue_tile = [&](int i) {
            int k0 = (kti + i) * BK;
            uint32_t abase = smb + (uint32_t)((i & 1) * STAGE_BYTES);
            uint32_t bbase = abase + A_BYTES;
            const bool interior = !m_edge && (k0 + BK <= NP);
            if (interior) {
#pragma unroll
                for (int j = 0; j < 8; j++) {
                    int q = j * 256 + t;
                    int r = q >> 4, c = q & 15;
                    CPA16U(abase + (uint32_t)(r * AROW + c * 4) * 4,
                           A + (size_t)(row0 + r) * NP + k0 + c * 4);
                }
            } else {
#pragma unroll
                for (int j = 0; j < 8; j++) {
                    int q = j * 256 + t;
                    int r = q >> 4, c = q & 15;
                    int grow = row0 + r, gk = k0 + c * 4;
                    uint32_t sz = (grow < NP && gk < NP) ? 16u : 0u;
                    CPA16(abase + (uint32_t)(r * AROW + c * 4) * 4,
                          A + (size_t)grow * NP + gk, sz);
                }
            }
            // B: 48 rows x 64 halfs = 384 16B chunks (pad cols are zero)
#pragma unroll
            for (int jj = 0; jj < 2; jj++) {
                int q = jj * 256 + t;
                if (q < 384) {
                    int r = q >> 3, sg2 = q & 7;
                    CPA16U(bbase + (uint32_t)(r * BROW + sg2 * 8) * 2,
                           g_bh + (size_t)r * BPAD + k0 + sg2 * 8);
                }
            }
            CPA_COMMIT();
        };

        issue_tile(0);
        if (seg > 1) issue_tile(1);
        else CPA_COMMIT();

        for (int i = 0; i < seg; i++) {
            if (i + 1 < seg) {
                asm volatile("cp.async.wait_group 1;" ::: "memory");
            } else {
                asm volatile("cp.async.wait_group 0;" ::: "memory");
            }
            __syncthreads();

            const float* smA = reinterpret_cast<const float*>(dsm + (i & 1) * STAGE_BYTES);
            const uint32_t bb2 = smb + (uint32_t)((i & 1) * STAGE_BYTES) + A_BYTES;

#pragma unroll
            for (int ks = 0; ks < 4; ks++) {
                const int c0 = ks * 16 + tig * 2;
                const float2 v0 = *reinterpret_cast<const float2*>(&smA[(w * 16 + g) * AROW + c0]);
                const float2 v1 = *reinterpret_cast<const float2*>(&smA[(w * 16 + g + 8) * AROW + c0]);
                const float2 v2 = *reinterpret_cast<const float2*>(&smA[(w * 16 + g) * AROW + c0 + 8]);
                const float2 v3 = *reinterpret_cast<const float2*>(&smA[(w * 16 + g + 8) * AROW + c0 + 8]);
                uint32_t a0, a1, a2, a3;
                CVT_H2(a0, v0.y, v0.x);
                CVT_H2(a1, v1.y, v1.x);
                CVT_H2(a2, v2.y, v2.x);
                CVT_H2(a3, v3.y, v3.x);
                int kk = ks * 16;
#pragma unroll
                for (int ntp = 0; ntp < 3; ntp++) {
                    uint32_t b0, b1, b2, b3;
                    uint32_t boff = (uint32_t)(b_off + ntp * 16 * BROW + kk) * 2;
                    LDSM4(b0, b1, b2, b3, bb2 + boff);
                    MMA(acc[ntp * 2],     a0, a1, a2, a3, b0, b1);
                    MMA(acc[ntp * 2 + 1], a0, a1, a2, a3, b2, b3);
                }
            }
            // stage (i&1) fully consumed; refill with tile i+2
            __syncthreads();
            if (i + 2 < seg) issue_tile(i + 2);
        }

        const int v0r = row0 + w * 16 + g;
#pragma unroll
        for (int nt = 0; nt < 6; nt++) {
            int c0 = nt * 8 + tig * 2;
#pragma unroll
            for (int half = 0; half < 2; half++) {
                int v = v0r + half * 8;
                if (v < NP) {
#pragma unroll
                    for (int e2 = 0; e2 < 2; e2++) {
                        int c = c0 + e2;
                        int bo = c / 3, e = c - bo * 3;
                        atomicAdd(out + (size_t)bo * NP * 3 + (size_t)v * 3 + e,
                                  acc[nt][half * 2 + e2]);
                    }
                }
            }
        }

        start += seg;
        remn  -= seg;
        if (remn > 0) __syncthreads();
    }
}

// ---------------------------------------------------------------------------
extern "C" void kernel_launch(void* const* d_in, const int* in_sizes, int n_in,
                              void* d_out, int out_size) {
    const float* geo   = (const float*)d_in[0];
    const int*   nb    = (const int*)d_in[1];
    const float* recon = (const float*)d_in[2];
    const float* vdiff = (const float*)d_in[3];
    float* out = (float*)d_out;

    cudaFuncSetAttribute(gemm_mma, cudaFuncAttributeMaxDynamicSharedMemorySize,
                         DSMEM);

    ftoT_kernel<<<NP / 16, 256>>>(geo, reinterpret_cast<float4*>(out));
    bvec_kernel<<<NP / 16, 256>>>(nb, vdiff);
    gemm_mma<<<NCTA, 256, DSMEM>>>(recon, out);
}

// round 15
// speedup vs baseline: 1.1676x; 1.0180x over previous
#include <cuda_runtime.h>
#include <cuda_fp16.h>
#include <math.h>
#include <stdint.h>

#define BATCH 16
#define NP    10000
#define NNB   10
#define NCOL  48
#define BPAD  10048          // padded K for B operand (multiple of 64)
#define BK    64
#define NKT   157            // ceil(10000/64)
#define MT    128
#define NMT   79
#define TILES_TOTAL (NMT * NKT)   // 12403
#define NCTA  296            // 148 SMs x 2 CTAs
#define WBASE (TILES_TOTAL / NCTA)        // 41
#define WREM  (TILES_TOTAL - WBASE * NCTA) // 267

// GEMM smem geometry
#define AROW  72                       // A row stride in fp32 elems (288 B)
#define BROW  72                       // B row stride in fp16 elems (144 B)
#define A_BYTES (128 * AROW * 4)       // 36864
#define B_BYTES (NCOL * BROW * 2)      // 6912
#define STAGE_BYTES (A_BYTES + B_BYTES)  // 43776
#define NSTAGE 2
#define DSMEM (NSTAGE * STAGE_BYTES)   // 87552 -> 2 CTAs/SM

// ---------------- scratch (__device__ globals; zero-init) ------------------
__device__ __align__(16) float g_T[NP * BATCH * 9];   // [p][b][9]
__device__ __align__(16) __half g_bh[NCOL * BPAD];    // B fp16 [c][k]

__device__ __forceinline__ uint32_t smem_u32(const void* p) {
    uint32_t a;
    asm("{ .reg .u64 t; cvta.to.shared.u64 t, %1; cvt.u32.u64 %0, t; }"
        : "=r"(a) : "l"(p));
    return a;
}

#define LDSM4(r0, r1, r2, r3, addr) \
    asm volatile("ldmatrix.sync.aligned.m8n8.x4.shared.b16 {%0,%1,%2,%3}, [%4];" \
                 : "=r"(r0), "=r"(r1), "=r"(r2), "=r"(r3) : "r"(addr))

#define MMA(d, a0, a1, a2, a3, b0, b1) \
    asm volatile("mma.sync.aligned.m16n8k16.row.col.f32.f16.f16.f32 " \
                 "{%0,%1,%2,%3}, {%4,%5,%6,%7}, {%8,%9}, {%0,%1,%2,%3};" \
                 : "+f"((d)[0]), "+f"((d)[1]), "+f"((d)[2]), "+f"((d)[3]) \
                 : "r"(a0), "r"(a1), "r"(a2), "r"(a3), "r"(b0), "r"(b1))

#define CVT_H2(d, hi, lo) \
    asm("cvt.rn.f16x2.f32 %0, %1, %2;" : "=r"(d) : "f"(hi), "f"(lo))

#define CPA16(dst, src, sz) \
    asm volatile("cp.async.cg.shared.global [%0], [%1], 16, %2;" \
                 :: "r"(dst), "l"(src), "r"(sz) : "memory")
#define CPA16U(dst, src) \
    asm volatile("cp.async.cg.shared.global [%0], [%1], 16;" \
                 :: "r"(dst), "l"(src) : "memory")
#define CPA_COMMIT() asm volatile("cp.async.commit_group;" ::: "memory")

#define GDC_WAIT() asm volatile("griddepcontrol.wait;" ::: "memory")
#define GDC_LAUNCH() asm volatile("griddepcontrol.launch_dependents;" ::: "memory")

// ---------------------------------------------------------------------------
// Kernel 1: T[b,p] = R @ S; store [p][b][9]. Zeroes output.
// ---------------------------------------------------------------------------
__global__ __launch_bounds__(256) void ftoT_kernel(const float* __restrict__ geo,
                                                   float4* __restrict__ outz) {
    __shared__ float sT[16 * 145];

    const int tid = threadIdx.x;
    const int bb = tid >> 4;
    const int pi = tid & 15;
    const int p0 = blockIdx.x * 16;
    const int p  = p0 + pi;

    {
        int g = blockIdx.x * 256 + tid;
        if (g < 120000)
            outz[g] = make_float4(0.f, 0.f, 0.f, 0.f);
    }

    const float* f = geo + (size_t)(bb * NP + p) * 9;
    float x = f[0], y = f[1], z = f[2];
    float s3 = f[3], s4 = f[4], s5 = f[5], s6 = f[6], s7 = f[7], s8 = f[8];

    float th = sqrtf(x * x + y * y + z * z);
    float R00, R01, R02, R10, R11, R12, R20, R21, R22;
    if (th == 0.0f) {
        R00 = 1.f; R01 = 0.f; R02 = 0.f;
        R10 = 0.f; R11 = 1.f; R12 = 0.f;
        R20 = 0.f; R21 = 0.f; R22 = 1.f;
    } else {
        float inv = 1.0f / th;
        float ka = x * inv, kb = y * inv, kc = z * inv;
        float st, ct;
        __sincosf(th, &st, &ct);
        float omc = 1.0f - ct;
        R00 = 1.0f - omc * (ka * ka + kb * kb);
        R01 =  st * ka - omc * kb * kc;
        R02 =  st * kb + omc * ka * kc;
        R10 = -st * ka - omc * kb * kc;
        R11 = 1.0f - omc * (ka * ka + kc * kc);
        R12 =  st * kc - omc * ka * kb;
        R20 = -st * kb + omc * ka * kc;
        R21 = -st * kc - omc * ka * kb;
        R22 = 1.0f - omc * (kb * kb + kc * kc);
    }
    float* o = sT + pi * 145 + bb * 9;
    o[0] = R00 * s3 + R01 * s4 + R02 * s5;
    o[1] = R00 * s4 + R01 * s6 + R02 * s7;
    o[2] = R00 * s5 + R01 * s7 + R02 * s8;
    o[3] = R10 * s3 + R11 * s4 + R12 * s5;
    o[4] = R10 * s4 + R11 * s6 + R12 * s7;
    o[5] = R10 * s5 + R11 * s7 + R12 * s8;
    o[6] = R20 * s3 + R21 * s4 + R22 * s5;
    o[7] = R20 * s4 + R21 * s6 + R22 * s7;
    o[8] = R20 * s5 + R21 * s7 + R22 * s8;
    __syncthreads();

    float4* dst = reinterpret_cast<float4*>(g_T + (size_t)p0 * 144);
#pragma unroll
    for (int q = tid; q < 576; q += 256) {
        int prow = q / 36;
        int s = q - prow * 36;
        const float* sp = sT + prow * 145 + s * 4;
        dst[q] = make_float4(sp[0], sp[1], sp[2], sp[3]);
    }
    GDC_LAUNCH();
}

// ---------------------------------------------------------------------------
// Kernel 2: bvec (PDL: overlaps ftoT; triggers gemm early).
// ---------------------------------------------------------------------------
__global__ __launch_bounds__(256) void bvec_kernel(const int* __restrict__ nb,
                                                   const float* __restrict__ vdiff) {
    __shared__ int   s_nb[160];    // 16 p x 10
    __shared__ float s_vd[480];    // 16 p x 30

    const int tid = threadIdx.x;
    const int bb = tid & 15;
    const int pi = tid >> 4;
    const int p0 = blockIdx.x * 16;
    const int p  = p0 + pi;

    // independent staging (may run while ftoT still executes)
    if (tid < 160) s_nb[tid] = __ldg(nb + p0 * NNB + tid);
    if (tid < 120) {
        float4 v = __ldg(reinterpret_cast<const float4*>(vdiff + (size_t)p0 * 30) + tid);
        *reinterpret_cast<float4*>(&s_vd[tid * 4]) = v;
    }
    GDC_LAUNCH();     // let gemm grid launch and start its A-prefetch
    GDC_WAIT();       // g_T must be complete before gathers
    __syncthreads();

    const float* Tp = g_T + ((size_t)p * BATCH + bb) * 9;
    float T0 = Tp[0], T1 = Tp[1], T2 = Tp[2];
    float T3 = Tp[3], T4 = Tp[4], T5 = Tp[5];
    float T6 = Tp[6], T7 = Tp[7], T8 = Tp[8];

    float a0 = 0.f, a1 = 0.f, a2 = 0.f;
    float v0s = 0.f, v1s = 0.f, v2s = 0.f;

#pragma unroll
    for (int n = 0; n < NNB; n++) {
        int idx = s_nb[pi * NNB + n];
        float v0 = s_vd[pi * 30 + n * 3 + 0];
        float v1 = s_vd[pi * 30 + n * 3 + 1];
        float v2 = s_vd[pi * 30 + n * 3 + 2];
        v0s += v0; v1s += v1; v2s += v2;
        if (idx > 0) {
            const float* Tn = g_T + ((size_t)(idx - 1) * BATCH + bb) * 9;
            a0 += Tn[0] * v0 + Tn[1] * v1 + Tn[2] * v2;
            a1 += Tn[3] * v0 + Tn[4] * v1 + Tn[5] * v2;
            a2 += Tn[6] * v0 + Tn[7] * v1 + Tn[8] * v2;
        }
    }
    a0 += T0 * v0s + T1 * v1s + T2 * v2s;
    a1 += T3 * v0s + T4 * v1s + T5 * v2s;
    a2 += T6 * v0s + T7 * v1s + T8 * v2s;

    int c = bb * 3;
    g_bh[(size_t)(c + 0) * BPAD + p] = __float2half_rn(a0);
    g_bh[(size_t)(c + 1) * BPAD + p] = __float2half_rn(a1);
    g_bh[(size_t)(c + 2) * BPAD + p] = __float2half_rn(a2);
}

// ---------------------------------------------------------------------------
// Kernel 3: stream-K fp16 GEMM, BK=64, 2-stage, 2 CTAs/SM.
// PDL: A-prefetch of first two tiles before griddepcontrol.wait.
// ---------------------------------------------------------------------------
__global__ __launch_bounds__(256, 2) void gemm_mma(const float* __restrict__ A,
                                                   float* __restrict__ out) {
    extern __shared__ __align__(16) char dsm[];

    const int t = threadIdx.x;
    const int w = t >> 5;
    const int l = t & 31;

    const int g   = l >> 2;
    const int tig = l & 3;
    const int mat = l >> 3, mrow = l & 7;

    const uint32_t smb = smem_u32(dsm);
    const int b_off = (((mat >> 1) << 3) + mrow) * BROW + ((mat & 1) << 3);

    const int ct = blockIdx.x;
    int start = ct * WBASE + (ct < WREM ? ct : WREM);
    int remn  = WBASE + (ct < WREM ? 1 : 0);
    bool first = true;

    while (remn > 0) {
        const int m   = start / NKT;
        const int kti = start - m * NKT;
        int seg = NKT - kti; if (seg > remn) seg = remn;
        const int row0 = m * MT;
        const bool m_edge = (row0 + MT > NP);

        float acc[6][4];
#pragma unroll
        for (int i = 0; i < 6; i++)
#pragma unroll
            for (int j = 0; j < 4; j++) acc[i][j] = 0.f;

        auto issue_A = [&](int i) {
            int k0 = (kti + i) * BK;
            uint32_t abase = smb + (uint32_t)((i & 1) * STAGE_BYTES);
            const bool interior = !m_edge && (k0 + BK <= NP);
            if (interior) {
#pragma unroll
                for (int j = 0; j < 8; j++) {
                    int q = j * 256 + t;
                    int r = q >> 4, c = q & 15;
                    CPA16U(abase + (uint32_t)(r * AROW + c * 4) * 4,
                           A + (size_t)(row0 + r) * NP + k0 + c * 4);
                }
            } else {
#pragma unroll
                for (int j = 0; j < 8; j++) {
                    int q = j * 256 + t;
                    int r = q >> 4, c = q & 15;
                    int grow = row0 + r, gk = k0 + c * 4;
                    uint32_t sz = (grow < NP && gk < NP) ? 16u : 0u;
                    CPA16(abase + (uint32_t)(r * AROW + c * 4) * 4,
                          A + (size_t)grow * NP + gk, sz);
                }
            }
        };
        auto issue_B = [&](int i) {
            int k0 = (kti + i) * BK;
            uint32_t bbase = smb + (uint32_t)((i & 1) * STAGE_BYTES) + A_BYTES;
#pragma unroll
            for (int jj = 0; jj < 2; jj++) {
                int q = jj * 256 + t;
                if (q < 384) {
                    int r = q >> 3, sg2 = q & 7;
                    CPA16U(bbase + (uint32_t)(r * BROW + sg2 * 8) * 2,
                           g_bh + (size_t)r * BPAD + k0 + sg2 * 8);
                }
            }
        };

        if (first) {
            // A-prefetch may run concurrently with bvec (PDL)
            issue_A(0);
            if (seg > 1) issue_A(1);
            GDC_WAIT();                  // g_bh ready beyond this point
            issue_B(0); CPA_COMMIT();    // group0 = A0[,A1],B0
            if (seg > 1) { issue_B(1); CPA_COMMIT(); }   // group1 = B1
            else CPA_COMMIT();
            first = false;
        } else {
            issue_A(0); issue_B(0); CPA_COMMIT();
            if (seg > 1) { issue_A(1); issue_B(1); CPA_COMMIT(); }
            else CPA_COMMIT();
        }

        for (int i = 0; i < seg; i++) {
            if (i + 1 < seg) {
                asm volatile("cp.async.wait_group 1;" ::: "memory");
            } else {
                asm volatile("cp.async.wait_group 0;" ::: "memory");
            }
            __syncthreads();

            const float* smA = reinterpret_cast<const float*>(dsm + (i & 1) * STAGE_BYTES);
            const uint32_t bb2 = smb + (uint32_t)((i & 1) * STAGE_BYTES) + A_BYTES;

#pragma unroll
            for (int ks = 0; ks < 4; ks++) {
                const int c0 = ks * 16 + tig * 2;
                const float2 v0 = *reinterpret_cast<const float2*>(&smA[(w * 16 + g) * AROW + c0]);
                const float2 v1 = *reinterpret_cast<const float2*>(&smA[(w * 16 + g + 8) * AROW + c0]);
                const float2 v2 = *reinterpret_cast<const float2*>(&smA[(w * 16 + g) * AROW + c0 + 8]);
                const float2 v3 = *reinterpret_cast<const float2*>(&smA[(w * 16 + g + 8) * AROW + c0 + 8]);
                uint32_t a0, a1, a2, a3;
                CVT_H2(a0, v0.y, v0.x);
                CVT_H2(a1, v1.y, v1.x);
                CVT_H2(a2, v2.y, v2.x);
                CVT_H2(a3, v3.y, v3.x);
                int kk = ks * 16;
#pragma unroll
                for (int ntp = 0; ntp < 3; ntp++) {
                    uint32_t b0, b1, b2, b3;
                    uint32_t boff = (uint32_t)(b_off + ntp * 16 * BROW + kk) * 2;
                    LDSM4(b0, b1, b2, b3, bb2 + boff);
                    MMA(acc[ntp * 2],     a0, a1, a2, a3, b0, b1);
                    MMA(acc[ntp * 2 + 1], a0, a1, a2, a3, b2, b3);
                }
            }
            __syncthreads();
            if (i + 2 < seg) { issue_A(i + 2); issue_B(i + 2); CPA_COMMIT(); }
        }

        const int v0r = row0 + w * 16 + g;
#pragma unroll
        for (int nt = 0; nt < 6; nt++) {
            int c0 = nt * 8 + tig * 2;
#pragma unroll
            for (int half = 0; half < 2; half++) {
                int v = v0r + half * 8;
                if (v < NP) {
#pragma unroll
                    for (int e2 = 0; e2 < 2; e2++) {
                        int c = c0 + e2;
                        int bo = c / 3, e = c - bo * 3;
                        atomicAdd(out + (size_t)bo * NP * 3 + (size_t)v * 3 + e,
                                  acc[nt][half * 2 + e2]);
                    }
                }
            }
        }

        start += seg;
        remn  -= seg;
        if (remn > 0) __syncthreads();
    }
}

// ---------------------------------------------------------------------------
extern "C" void kernel_launch(void* const* d_in, const int* in_sizes, int n_in,
                              void* d_out, int out_size) {
    const float* geo   = (const float*)d_in[0];
    const int*   nb    = (const int*)d_in[1];
    const float* recon = (const float*)d_in[2];
    const float* vdiff = (const float*)d_in[3];
    float* out = (float*)d_out;

    cudaFuncSetAttribute(gemm_mma, cudaFuncAttributeMaxDynamicSharedMemorySize,
                         DSMEM);

    ftoT_kernel<<<NP / 16, 256>>>(geo, reinterpret_cast<float4*>(out));

    cudaLaunchAttribute attr[1];
    attr[0].id = cudaLaunchAttributeProgrammaticStreamSerialization;
    attr[0].val.programmaticStreamSerializationAllowed = 1;

    {   // bvec with PDL (overlaps ftoT tail)
        cudaLaunchConfig_t cfg = {};
        cfg.gridDim = dim3(NP / 16, 1, 1);
        cfg.blockDim = dim3(256, 1, 1);
        cfg.dynamicSmemBytes = 0;
        cfg.stream = 0;
        cfg.attrs = attr;
        cfg.numAttrs = 1;
        cudaLaunchKernelEx(&cfg, bvec_kernel, nb, vdiff);
    }
    {   // gemm with PDL (overlaps bvec with A-prefetch)
        cudaLaunchConfig_t cfg = {};
        cfg.gridDim = dim3(NCTA, 1, 1);
        cfg.blockDim = dim3(256, 1, 1);
        cfg.dynamicSmemBytes = DSMEM;
        cfg.stream = 0;
        cfg.attrs = attr;
        cfg.numAttrs = 1;
        cudaLaunchKernelEx(&cfg, gemm_mma, recon, out);
    }
}